// round 13
// baseline (speedup 1.0000x reference)
#include <cuda_runtime.h>
#include <stdint.h>

// ---------------- problem constants ----------------
#define BATCH 128
#define TSTEPS 300
#define CLIP 50
#define DIN 2312
#define DINP 2320          // K padded (zero-padded; FFMA +0 is exact)
#define HID 800
#define HIDP 896
#define NC 10
#define MROWS (BATCH*CLIP) // 6400
#define MROWS2 (2*MROWS)   // duplicated-A row length
#define NCH (DINP/16)      // 145 k-chunks of 16

// ---------------- scratch ----------------
__device__ float g_XcT[(size_t)DINP * MROWS2]; // A^T dup [2320][12800]: m pairs (a,a)
__device__ float g_Bt[(size_t)DINP * HIDP];    // B^T [2320][896]  (k-major)
__device__ float g_V1[(size_t)MROWS * HIDP];   // V1 [6400][896]

// ---------------- PTX helpers ----------------
typedef unsigned long long ull;
__device__ __forceinline__ uint32_t smem_u32(const void* p) {
    uint32_t a;
    asm("{ .reg .u64 t; cvta.to.shared.u64 t, %1; cvt.u32.u64 %0, t; }" : "=r"(a) : "l"(p));
    return a;
}
__device__ __forceinline__ void cp_async16(uint32_t dst, const void* src) {
    asm volatile("cp.async.cg.shared.global [%0], [%1], 16;" :: "r"(dst), "l"(src));
}
#define CP_COMMIT() asm volatile("cp.async.commit_group;" ::: "memory")
__device__ __forceinline__ void ffma2(ull& d, ull a, ull b) {
    asm("fma.rn.f32x2 %0, %1, %2, %0;" : "+l"(d) : "l"(a), "l"(b));
}

// ---------------- kernel 1: paste X into output ----------------
__global__ void paste_kernel(const float* __restrict__ inp,
                             const int* __restrict__ idx,
                             float* __restrict__ outX) {
    long tid = (long)blockIdx.x * blockDim.x + threadIdx.x;
    const long total = (long)BATCH * DIN * (TSTEPS / 4);
    if (tid >= total) return;
    int  c4  = (int)(tid % (TSTEPS / 4));
    long row = tid / (TSTEPS / 4);
    int  i   = (int)(row / DIN);
    int  d   = (int)(row % DIN);
    int  t0  = c4 * 4;
    int  id  = idx[i];
    float4 v;
    float* vv = (float*)&v;
    const float* src = inp + (long)i * DIN * CLIP + (long)d * CLIP;
#pragma unroll
    for (int u = 0; u < 4; u++) {
        int s = t0 + u - id;
        vv[u] = (s >= 0 && s < CLIP) ? src[s] : 0.f;
    }
    *(float4*)&outX[row * TSTEPS + t0] = v;
}

// ---------------- kernel 2: clips -> XcT dup [2320][12800] ----------------
__global__ void transposeA_kernel(const float* __restrict__ inp) {
    __shared__ float tile[32][51];
    int i  = blockIdx.x;
    int d0 = blockIdx.y * 32;
    int tid = threadIdx.x;  // 256
    for (int p = tid; p < 32 * CLIP; p += 256) {
        int dd = p / CLIP, s = p % CLIP;
        int d = d0 + dd;
        tile[dd][s] = (d < DIN) ? inp[((long)i * DIN + d) * CLIP + s] : 0.f;
    }
    __syncthreads();
    for (int p = tid; p < 32 * CLIP; p += 256) {
        int dd = p / CLIP, s = p % CLIP;
        int d = d0 + dd;
        if (d < DINP) {
            float v = tile[dd][s];
            *(float2*)&g_XcT[(long)d * MROWS2 + (long)(i * CLIP + s) * 2] =
                make_float2(v, v);
        }
    }
}

// ---------------- kernel 3: W1 -> Bt [2320][896] coalesced transpose ----------
__global__ void transposeB_kernel(const float* __restrict__ W1) {
    __shared__ float tile[32][33];
    int k0 = blockIdx.x * 32;
    int n0 = blockIdx.y * 32;
    int tx = threadIdx.x & 31;
    int ty = threadIdx.x >> 5;     // 0..7
#pragma unroll
    for (int r = 0; r < 4; r++) {
        int n = n0 + ty + r * 8;
        int k = k0 + tx;
        tile[ty + r * 8][tx] = (n < HID && k < DIN) ? W1[(long)n * DIN + k] : 0.f;
    }
    __syncthreads();
#pragma unroll
    for (int r = 0; r < 4; r++) {
        int k = k0 + ty + r * 8;
        int n = n0 + tx;
        if (k < DINP && n < HIDP)
            g_Bt[(long)k * HIDP + n] = tile[tx][ty + r * 8];
    }
}

// ---------------- kernel 4: fp32x2 FFMA GEMM v7 (bit-identical k-order) -------
// BM=32, BN=128, BK=16, 128 threads, 3-stage cp.async, grid 1400, occ 5.
// A duplicated in smem -> no pack2 movs; B conflict-free LDS.128.
#define BK 16
#define NST 3
#define A_STG 4096                 // 16 kk * 256B (32 m duplicated)
#define B_STG 8192                 // 16 kk * 512B (128 n)
#define STG (A_STG + B_STG)        // 12288
#define GEMM_SMEM (NST * STG)      // 36864

__global__ __launch_bounds__(128, 5) void gemm_kernel() {
    extern __shared__ char dsm[];
    uint32_t sb = smem_u32(dsm);
    int tid = threadIdx.x;
    int m0 = blockIdx.x * 32;
    int n0 = blockIdx.y * 128;
    int tx = tid & 15;         // 16 over N (8 cols each)
    int ty = tid >> 4;         // 8 over M (4 rows each)

    ull acc[4][4];
#pragma unroll
    for (int r = 0; r < 4; r++)
#pragma unroll
        for (int q = 0; q < 4; q++) acc[r][q] = 0ull;

    const float* Ab = g_XcT + (long)m0 * 2;
    const float* Bb = g_Bt + n0;

    // prologue: chunks 0..NST-2
#pragma unroll
    for (int c = 0; c < NST - 1; ++c) {
        uint32_t st = sb + c * STG;
        long k0 = (long)c * BK;
#pragma unroll
        for (int j = 0; j < 2; ++j) {         // A dup: 256 items of 16B
            int id = tid + 128 * j;
            int kk = id >> 4, cc = id & 15;
            cp_async16(st + kk * 256 + cc * 16,
                       Ab + (k0 + kk) * MROWS2 + cc * 4);
        }
#pragma unroll
        for (int j = 0; j < 4; ++j) {         // B: 512 items of 16B
            int id = tid + 128 * j;
            int kk = id >> 5, cc = id & 31;
            cp_async16(st + A_STG + kk * 512 + cc * 16,
                       Bb + (k0 + kk) * HIDP + cc * 4);
        }
        CP_COMMIT();
    }

    for (int c = 0; c < NCH; ++c) {
        int cl = c + NST - 1;
        if (cl < NCH) {
            uint32_t st = sb + (cl % NST) * STG;
            long k0 = (long)cl * BK;
#pragma unroll
            for (int j = 0; j < 2; ++j) {
                int id = tid + 128 * j;
                int kk = id >> 4, cc = id & 15;
                cp_async16(st + kk * 256 + cc * 16,
                           Ab + (k0 + kk) * MROWS2 + cc * 4);
            }
#pragma unroll
            for (int j = 0; j < 4; ++j) {
                int id = tid + 128 * j;
                int kk = id >> 5, cc = id & 31;
                cp_async16(st + A_STG + kk * 512 + cc * 16,
                           Bb + (k0 + kk) * HIDP + cc * 4);
            }
        }
        CP_COMMIT();
        asm volatile("cp.async.wait_group %0;" :: "n"(NST - 1) : "memory");
        __syncthreads();

        const char* aT = dsm + (c % NST) * STG;
        const char* bT = aT + A_STG;
#pragma unroll
        for (int kk = 0; kk < BK; ++kk) {
            ulonglong2 av0 = *(const ulonglong2*)(aT + kk * 256 + ty * 32);
            ulonglong2 av1 = *(const ulonglong2*)(aT + kk * 256 + ty * 32 + 16);
            ulonglong2 bv0 = *(const ulonglong2*)(bT + kk * 512 + tx * 16);
            ulonglong2 bv1 = *(const ulonglong2*)(bT + kk * 512 + 256 + tx * 16);
            ull ar[4] = {av0.x, av0.y, av1.x, av1.y};
            ull bq[4] = {bv0.x, bv0.y, bv1.x, bv1.y};
#pragma unroll
            for (int r = 0; r < 4; r++)
#pragma unroll
                for (int q = 0; q < 4; q++)
                    ffma2(acc[r][q], ar[r], bq[q]);
        }
        __syncthreads();
    }

    // epilogue
#pragma unroll
    for (int r = 0; r < 4; r++) {
        long m = m0 + ty * 4 + r;
        float2 f0 = *(float2*)&acc[r][0];
        float2 f1 = *(float2*)&acc[r][1];
        float2 f2 = *(float2*)&acc[r][2];
        float2 f3 = *(float2*)&acc[r][3];
        *(float4*)&g_V1[m * HIDP + n0 + tx * 4]      = make_float4(f0.x, f0.y, f1.x, f1.y);
        *(float4*)&g_V1[m * HIDP + n0 + 64 + tx * 4] = make_float4(f2.x, f2.y, f3.x, f3.y);
    }
}

// ---------------- kernel 5: scan v3 — single barrier, replicated controller ---
__global__ __launch_bounds__(256, 1) void scan_kernel(
    const int*   __restrict__ idx,
    const float* __restrict__ b1,
    const float* __restrict__ W2,
    const float* __restrict__ b2,
    const float* __restrict__ Wc,
    const float* __restrict__ bc,
    float*       __restrict__ out)
{
    __shared__ float wpart[2][8][11];

    int i   = blockIdx.x;
    int tid = threadIdx.x;

    int  jj[4]; bool jv[4];
#pragma unroll
    for (int r = 0; r < 4; r++) { jj[r] = tid + 256 * r; jv[r] = (jj[r] < HID); }

    float w2r[4][NC], wcr[4], b1r[4];
#pragma unroll
    for (int r = 0; r < 4; r++) {
        if (jv[r]) {
#pragma unroll
            for (int k = 0; k < NC; k++) w2r[r][k] = W2[k * HID + jj[r]];
            wcr[r] = Wc[jj[r]];
            b1r[r] = b1[jj[r]];
        } else {
#pragma unroll
            for (int k = 0; k < NC; k++) w2r[r][k] = 0.f;
            wcr[r] = 0.f; b1r[r] = 0.f;
        }
    }

    float h1m[4] = {0.f, 0.f, 0.f, 0.f};
    float h1s[4] = {0.f, 0.f, 0.f, 0.f};

    float cm = 0.f, cs = 0.f, bgt = 1.f;
    float wc0 = Wc[800], wc1 = Wc[801], wc2 = Wc[802], wc3 = Wc[803];
    float bc0 = bc[0];

    float h2m = 0.f, h2s = 0.f, sum2 = 0.f, my_b2 = 0.f;
    if (tid < 10) my_b2 = b2[tid];

    int myidx = idx[i];
    const float* v1base = &g_V1[(long)i * CLIP * HIDP];

    float vp[4] = {0.f, 0.f, 0.f, 0.f};
    {
        int s0 = 0 - myidx;
        if (s0 >= 0 && s0 < CLIP) {
            const float* v1 = v1base + (long)s0 * HIDP;
#pragma unroll
            for (int r = 0; r < 4; r++) if (jv[r]) vp[r] = v1[jj[r]];
        }
    }

    for (int t = 0; t < TSTEPS; t++) {
        float g = (t == 0) ? 1.f : cs;
        int s = t - myidx;
        bool act = (s >= 0) && (s < CLIP) && (g != 0.f);

        float part[11];
#pragma unroll
        for (int k = 0; k < 11; k++) part[k] = 0.f;

#pragma unroll
        for (int r = 0; r < 4; r++) {
            if (jv[r]) {
                float v = act ? vp[r] : 0.f;   // gate is exactly 1 when act
                float m = h1m[r] * 0.1f * (1.f - h1s[r]) + v + b1r[r];
                h1m[r] = m;
                float sp = (m > 0.5f) ? 1.f : 0.f;
                h1s[r] = sp;
                if (sp != 0.f) {
#pragma unroll
                    for (int k = 0; k < 10; k++) part[k] += w2r[r][k];
                    part[10] += wcr[r];
                }
            }
        }

        float vn[4] = {0.f, 0.f, 0.f, 0.f};
        int sn = t + 1 - myidx;
        if (t + 1 < TSTEPS && sn >= 0 && sn < CLIP) {
            const float* v1n = v1base + (long)sn * HIDP;
#pragma unroll
            for (int r = 0; r < 4; r++) if (jv[r]) vn[r] = __ldg(&v1n[jj[r]]);
        }

#pragma unroll
        for (int k = 0; k < 11; k++) {
#pragma unroll
            for (int off = 16; off; off >>= 1)
                part[k] += __shfl_down_sync(0xffffffffu, part[k], off);
        }
        int buf = t & 1;
        if ((tid & 31) == 0) {
#pragma unroll
            for (int k = 0; k < 11; k++) wpart[buf][tid >> 5][k] = part[k];
        }
        __syncthreads();   // the ONLY barrier per step

        {
            float red = 0.f;
#pragma unroll
            for (int w = 0; w < 8; w++) red += wpart[buf][w][10];
            float csprev = cs;
            if (csprev == 1.f) bgt += 1.f;
            float fq = wc0
                     + (((t % 2)   == 0) ? wc1 : 0.f)
                     + (((t % 10)  == 0) ? wc2 : 0.f)
                     + (((t % 100) == 0) ? wc3 : 0.f);
            cm = cm * 0.1f * (1.f - csprev) + red + fq + bc0;
            cs = (cm > 0.5f) ? 1.f : 0.f;
        }

        if (tid < 10) {
            float red = 0.f;
#pragma unroll
            for (int w = 0; w < 8; w++) red += wpart[buf][w][tid];
            float m = h2m * 0.1f * (1.f - h2s) + red + my_b2;
            h2m = m;
            h2s = (m > 0.5f) ? 1.f : 0.f;
            sum2 += h2s;
        }

#pragma unroll
        for (int r = 0; r < 4; r++) vp[r] = vn[r];
    }

    if (tid < 10) out[i * NC + tid] = sum2 / bgt;
}

// ---------------- launcher ----------------
extern "C" void kernel_launch(void* const* d_in, const int* in_sizes, int n_in,
                              void* d_out, int out_size) {
    const float* inp = (const float*)d_in[0];
    const int*   idx = (const int*)d_in[2];
    const float* W1  = (const float*)d_in[3];
    const float* b1  = (const float*)d_in[4];
    const float* W2  = (const float*)d_in[5];
    const float* b2  = (const float*)d_in[6];
    const float* Wc  = (const float*)d_in[7];
    const float* bc  = (const float*)d_in[8];
    float* out = (float*)d_out;

    cudaFuncSetAttribute(gemm_kernel, cudaFuncAttributeMaxDynamicSharedMemorySize,
                         GEMM_SMEM);

    {
        long total = (long)BATCH * DIN * (TSTEPS / 4);
        paste_kernel<<<(int)((total + 255) / 256), 256>>>(inp, idx, out + BATCH * NC);
    }
    {
        dim3 grid(BATCH, (DINP + 31) / 32);
        transposeA_kernel<<<grid, 256>>>(inp);
    }
    {
        dim3 grid((DINP + 31) / 32, (HIDP + 31) / 32);
        transposeB_kernel<<<grid, 256>>>(W1);
    }
    {
        dim3 grid(MROWS / 32, HIDP / 128);
        gemm_kernel<<<grid, 128, GEMM_SMEM>>>();
    }
    scan_kernel<<<BATCH, 256>>>(idx, b1, W2, b2, Wc, bc, out);
}

// round 14
// speedup vs baseline: 1.7741x; 1.7741x over previous
#include <cuda_runtime.h>
#include <stdint.h>

// ---------------- problem constants ----------------
#define BATCH 128
#define TSTEPS 300
#define CLIP 50
#define DIN 2312
#define DINP 2320          // K padded (zero-padded; FFMA +0 is exact)
#define HID 800
#define HIDP 896
#define NC 10
#define MROWS (BATCH*CLIP) // 6400
#define NCH (DINP/16)      // 145 k-chunks of 16
#define IPB (DIN*75)       // 173400 float4 paste items per batch
#define NTOT4 (BATCH*IPB)  // 22,195,200 total paste items
#define NCTA 1400          // (6400/32) * (896/128)

// ---------------- scratch ----------------
__device__ float g_Xc[(size_t)DINP * MROWS];   // A^T [2320][6400] (k-major)
__device__ float g_Bt[(size_t)DINP * HIDP];    // B^T [2320][896]  (k-major)
__device__ float g_V1[(size_t)MROWS * HIDP];   // V1 [6400][896]

// ---------------- PTX helpers ----------------
typedef unsigned long long ull;
__device__ __forceinline__ uint32_t smem_u32(const void* p) {
    uint32_t a;
    asm("{ .reg .u64 t; cvta.to.shared.u64 t, %1; cvt.u32.u64 %0, t; }" : "=r"(a) : "l"(p));
    return a;
}
__device__ __forceinline__ void cp_async16(uint32_t dst, const void* src) {
    asm volatile("cp.async.cg.shared.global [%0], [%1], 16;" :: "r"(dst), "l"(src));
}
#define CP_COMMIT() asm volatile("cp.async.commit_group;" ::: "memory")
__device__ __forceinline__ void ffma2(ull& d, ull a, ull b) {
    asm("fma.rn.f32x2 %0, %1, %2, %0;" : "+l"(d) : "l"(a), "l"(b));
}
__device__ __forceinline__ ull pack2(float x) {
    ull r; asm("mov.b64 %0, {%1, %1};" : "=l"(r) : "f"(x)); return r;
}

// ---------------- kernel 2: clips -> Xc [2320][6400] (k-major) ----------------
__global__ void transposeA_kernel(const float* __restrict__ inp) {
    __shared__ float tile[32][51];
    int i  = blockIdx.x;
    int d0 = blockIdx.y * 32;
    int tid = threadIdx.x;  // 256
    for (int p = tid; p < 32 * CLIP; p += 256) {
        int dd = p / CLIP, s = p % CLIP;
        int d = d0 + dd;
        tile[dd][s] = (d < DIN) ? inp[((long)i * DIN + d) * CLIP + s] : 0.f;
    }
    __syncthreads();
    for (int p = tid; p < 32 * CLIP; p += 256) {
        int dd = p / CLIP, s = p % CLIP;
        int d = d0 + dd;
        if (d < DINP)
            g_Xc[(long)d * MROWS + i * CLIP + s] = tile[dd][s];
    }
}

// ---------------- kernel 3: W1 -> Bt [2320][896] coalesced transpose ----------
__global__ void transposeB_kernel(const float* __restrict__ W1) {
    __shared__ float tile[32][33];
    int k0 = blockIdx.x * 32;
    int n0 = blockIdx.y * 32;
    int tx = threadIdx.x & 31;
    int ty = threadIdx.x >> 5;     // 0..7
#pragma unroll
    for (int r = 0; r < 4; r++) {
        int n = n0 + ty + r * 8;
        int k = k0 + tx;
        tile[ty + r * 8][tx] = (n < HID && k < DIN) ? W1[(long)n * DIN + k] : 0.f;
    }
    __syncthreads();
#pragma unroll
    for (int r = 0; r < 4; r++) {
        int k = k0 + ty + r * 8;
        int n = n0 + tx;
        if (k < DINP && n < HIDP)
            g_Bt[(long)k * HIDP + n] = tile[tx][ty + r * 8];
    }
}

// ---------------- kernel 4: FFMA GEMM (round-12 core) + fused paste ----------
// BM=32, BN=128, BK=16, 128 threads, 3-stage cp.async, grid 1400, occ 4.
// Paste: 1 float4 item per thread per chunk, software-pipelined (load at c,
// store at c+1). Pure copy -> no FP order impact; V1 chain bit-identical.
#define BK 16
#define NST 3
#define A_STG 2048                 // 16 kk * 128B (32 m floats)
#define B_STG 8192                 // 16 kk * 512B (128 n)
#define STG (A_STG + B_STG)        // 10240
#define GEMM_SMEM (NST * STG)      // 30720

__global__ __launch_bounds__(128, 4) void gemm_kernel(
    const float* __restrict__ inp,
    const int*   __restrict__ idx,
    float*       __restrict__ outX)
{
    extern __shared__ char dsm[];
    uint32_t sb = smem_u32(dsm);
    int tid = threadIdx.x;
    int m0 = blockIdx.x * 32;
    int n0 = blockIdx.y * 128;
    int tx = tid & 15;         // 16 over N (8 cols each)
    int ty = tid >> 4;         // 8 over M (4 rows each)
    unsigned int Lt = (blockIdx.y * 200u + blockIdx.x) * 128u + (unsigned)tid;

    ull acc[4][4];
#pragma unroll
    for (int r = 0; r < 4; r++)
#pragma unroll
        for (int q = 0; q < 4; q++) acc[r][q] = 0ull;

    const float* Ab = g_Xc + m0;
    const float* Bb = g_Bt + n0;
    int akk = tid >> 3, acc4 = (tid & 7) * 4;   // A loader: 128 items of 16B

    // paste pipeline state
    float4 pv;
    float* pdst = 0;

    // prologue: chunks 0..NST-2
#pragma unroll
    for (int c = 0; c < NST - 1; ++c) {
        uint32_t st = sb + c * STG;
        long k0 = (long)c * BK;
        cp_async16(st + akk * 128 + acc4 * 4,
                   Ab + (k0 + akk) * MROWS + acc4);
#pragma unroll
        for (int j = 0; j < 4; ++j) {
            int id = tid + 128 * j;
            int kk = id >> 5, cc = id & 31;
            cp_async16(st + A_STG + kk * 512 + cc * 16,
                       Bb + (k0 + kk) * HIDP + cc * 4);
        }
        CP_COMMIT();
    }

    for (int c = 0; c < NCH; ++c) {
        int cl = c + NST - 1;
        if (cl < NCH) {
            uint32_t st = sb + (cl % NST) * STG;
            long k0 = (long)cl * BK;
            cp_async16(st + akk * 128 + acc4 * 4,
                       Ab + (k0 + akk) * MROWS + acc4);
#pragma unroll
            for (int j = 0; j < 4; ++j) {
                int id = tid + 128 * j;
                int kk = id >> 5, cc = id & 31;
                cp_async16(st + A_STG + kk * 512 + cc * 16,
                           Bb + (k0 + kk) * HIDP + cc * 4);
            }
        }
        CP_COMMIT();

        // ---- fused paste: store item loaded last chunk, load next item ----
        if (pdst) { *(float4*)pdst = pv; pdst = 0; }
        {
            unsigned int P = (unsigned)c * (NCTA * 128u) + Lt;
            if (P < NTOT4) {
                unsigned int i   = P / IPB;
                unsigned int rem = P - i * IPB;
                unsigned int d   = rem / 75u;
                unsigned int c4  = rem - d * 75u;
                int id = idx[i];
                const float* src = inp + ((long)i * DIN + d) * CLIP;
                float* vv = (float*)&pv;
#pragma unroll
                for (int u = 0; u < 4; u++) {
                    int ss = (int)c4 * 4 + u - id;
                    vv[u] = (ss >= 0 && ss < CLIP) ? src[ss] : 0.f;
                }
                pdst = &outX[((long)i * DIN + d) * TSTEPS + c4 * 4];
            }
        }

        asm volatile("cp.async.wait_group %0;" :: "n"(NST - 1) : "memory");
        __syncthreads();

        const char* aT = dsm + (c % NST) * STG;
        const char* bT = aT + A_STG;
#pragma unroll
        for (int kk = 0; kk < BK; ++kk) {
            float4 a = *(const float4*)(aT + kk * 128 + ty * 16);
            ulonglong2 bv0 = *(const ulonglong2*)(bT + kk * 512 + tx * 16);
            ulonglong2 bv1 = *(const ulonglong2*)(bT + kk * 512 + 256 + tx * 16);
            ull ar[4];
            ar[0] = pack2(a.x); ar[1] = pack2(a.y);
            ar[2] = pack2(a.z); ar[3] = pack2(a.w);
            ull bq[4] = {bv0.x, bv0.y, bv1.x, bv1.y};
#pragma unroll
            for (int r = 0; r < 4; r++)
#pragma unroll
                for (int q = 0; q < 4; q++)
                    ffma2(acc[r][q], ar[r], bq[q]);
        }
        __syncthreads();
    }

    // flush last paste item
    if (pdst) { *(float4*)pdst = pv; }

    // epilogue
#pragma unroll
    for (int r = 0; r < 4; r++) {
        long m = m0 + ty * 4 + r;
        float2 f0 = *(float2*)&acc[r][0];
        float2 f1 = *(float2*)&acc[r][1];
        float2 f2 = *(float2*)&acc[r][2];
        float2 f3 = *(float2*)&acc[r][3];
        *(float4*)&g_V1[m * HIDP + n0 + tx * 4]      = make_float4(f0.x, f0.y, f1.x, f1.y);
        *(float4*)&g_V1[m * HIDP + n0 + 64 + tx * 4] = make_float4(f2.x, f2.y, f3.x, f3.y);
    }
}

// ---------------- kernel 5: scan v3 — single barrier, replicated controller ---
__global__ __launch_bounds__(256, 1) void scan_kernel(
    const int*   __restrict__ idx,
    const float* __restrict__ b1,
    const float* __restrict__ W2,
    const float* __restrict__ b2,
    const float* __restrict__ Wc,
    const float* __restrict__ bc,
    float*       __restrict__ out)
{
    __shared__ float wpart[2][8][11];

    int i   = blockIdx.x;
    int tid = threadIdx.x;

    int  jj[4]; bool jv[4];
#pragma unroll
    for (int r = 0; r < 4; r++) { jj[r] = tid + 256 * r; jv[r] = (jj[r] < HID); }

    float w2r[4][NC], wcr[4], b1r[4];
#pragma unroll
    for (int r = 0; r < 4; r++) {
        if (jv[r]) {
#pragma unroll
            for (int k = 0; k < NC; k++) w2r[r][k] = W2[k * HID + jj[r]];
            wcr[r] = Wc[jj[r]];
            b1r[r] = b1[jj[r]];
        } else {
#pragma unroll
            for (int k = 0; k < NC; k++) w2r[r][k] = 0.f;
            wcr[r] = 0.f; b1r[r] = 0.f;
        }
    }

    float h1m[4] = {0.f, 0.f, 0.f, 0.f};
    float h1s[4] = {0.f, 0.f, 0.f, 0.f};

    float cm = 0.f, cs = 0.f, bgt = 1.f;
    float wc0 = Wc[800], wc1 = Wc[801], wc2 = Wc[802], wc3 = Wc[803];
    float bc0 = bc[0];

    float h2m = 0.f, h2s = 0.f, sum2 = 0.f, my_b2 = 0.f;
    if (tid < 10) my_b2 = b2[tid];

    int myidx = idx[i];
    const float* v1base = &g_V1[(long)i * CLIP * HIDP];

    float vp[4] = {0.f, 0.f, 0.f, 0.f};
    {
        int s0 = 0 - myidx;
        if (s0 >= 0 && s0 < CLIP) {
            const float* v1 = v1base + (long)s0 * HIDP;
#pragma unroll
            for (int r = 0; r < 4; r++) if (jv[r]) vp[r] = v1[jj[r]];
        }
    }

    for (int t = 0; t < TSTEPS; t++) {
        float g = (t == 0) ? 1.f : cs;
        int s = t - myidx;
        bool act = (s >= 0) && (s < CLIP) && (g != 0.f);

        float part[11];
#pragma unroll
        for (int k = 0; k < 11; k++) part[k] = 0.f;

#pragma unroll
        for (int r = 0; r < 4; r++) {
            if (jv[r]) {
                float v = act ? vp[r] : 0.f;   // gate is exactly 1 when act
                float m = h1m[r] * 0.1f * (1.f - h1s[r]) + v + b1r[r];
                h1m[r] = m;
                float sp = (m > 0.5f) ? 1.f : 0.f;
                h1s[r] = sp;
                if (sp != 0.f) {
#pragma unroll
                    for (int k = 0; k < 10; k++) part[k] += w2r[r][k];
                    part[10] += wcr[r];
                }
            }
        }

        float vn[4] = {0.f, 0.f, 0.f, 0.f};
        int sn = t + 1 - myidx;
        if (t + 1 < TSTEPS && sn >= 0 && sn < CLIP) {
            const float* v1n = v1base + (long)sn * HIDP;
#pragma unroll
            for (int r = 0; r < 4; r++) if (jv[r]) vn[r] = __ldg(&v1n[jj[r]]);
        }

#pragma unroll
        for (int k = 0; k < 11; k++) {
#pragma unroll
            for (int off = 16; off; off >>= 1)
                part[k] += __shfl_down_sync(0xffffffffu, part[k], off);
        }
        int buf = t & 1;
        if ((tid & 31) == 0) {
#pragma unroll
            for (int k = 0; k < 11; k++) wpart[buf][tid >> 5][k] = part[k];
        }
        __syncthreads();   // the ONLY barrier per step

        {
            float red = 0.f;
#pragma unroll
            for (int w = 0; w < 8; w++) red += wpart[buf][w][10];
            float csprev = cs;
            if (csprev == 1.f) bgt += 1.f;
            float fq = wc0
                     + (((t % 2)   == 0) ? wc1 : 0.f)
                     + (((t % 10)  == 0) ? wc2 : 0.f)
                     + (((t % 100) == 0) ? wc3 : 0.f);
            cm = cm * 0.1f * (1.f - csprev) + red + fq + bc0;
            cs = (cm > 0.5f) ? 1.f : 0.f;
        }

        if (tid < 10) {
            float red = 0.f;
#pragma unroll
            for (int w = 0; w < 8; w++) red += wpart[buf][w][tid];
            float m = h2m * 0.1f * (1.f - h2s) + red + my_b2;
            h2m = m;
            h2s = (m > 0.5f) ? 1.f : 0.f;
            sum2 += h2s;
        }

#pragma unroll
        for (int r = 0; r < 4; r++) vp[r] = vn[r];
    }

    if (tid < 10) out[i * NC + tid] = sum2 / bgt;
}

// ---------------- launcher ----------------
extern "C" void kernel_launch(void* const* d_in, const int* in_sizes, int n_in,
                              void* d_out, int out_size) {
    const float* inp = (const float*)d_in[0];
    const int*   idx = (const int*)d_in[2];
    const float* W1  = (const float*)d_in[3];
    const float* b1  = (const float*)d_in[4];
    const float* W2  = (const float*)d_in[5];
    const float* b2  = (const float*)d_in[6];
    const float* Wc  = (const float*)d_in[7];
    const float* bc  = (const float*)d_in[8];
    float* out = (float*)d_out;

    cudaFuncSetAttribute(gemm_kernel, cudaFuncAttributeMaxDynamicSharedMemorySize,
                         GEMM_SMEM);

    {
        dim3 grid(BATCH, (DINP + 31) / 32);
        transposeA_kernel<<<grid, 256>>>(inp);
    }
    {
        dim3 grid((DINP + 31) / 32, (HIDP + 31) / 32);
        transposeB_kernel<<<grid, 256>>>(W1);
    }
    {
        dim3 grid(MROWS / 32, HIDP / 128);
        gemm_kernel<<<grid, 128, GEMM_SMEM>>>(inp, idx, out + BATCH * NC);
    }
    scan_kernel<<<BATCH, 256>>>(idx, b1, W2, b2, Wc, bc, out);
}

// round 15
// speedup vs baseline: 1.8566x; 1.0465x over previous
#include <cuda_runtime.h>
#include <stdint.h>

// ---------------- problem constants ----------------
#define BATCH 128
#define TSTEPS 300
#define CLIP 50
#define DIN 2312
#define DINP 2320          // K padded (zero-padded; FFMA +0 is exact)
#define HID 800
#define HIDP 896
#define NC 10
#define MROWS (BATCH*CLIP) // 6400
#define NCH (DINP/16)      // 145 k-chunks of 16
#define IPB (DIN*75)       // 173400 float4 paste items per batch
#define NTOT4 ((unsigned)BATCH*IPB) // 22,195,200 paste items
#define NPCTA 168          // paste CTAs (grid = 128 scan + 168 paste = 296)

// ---------------- scratch ----------------
__device__ float g_Xc[(size_t)DINP * MROWS];   // A^T [2320][6400] (k-major)
__device__ float g_Bt[(size_t)DINP * HIDP];    // B^T [2320][896]  (k-major)
__device__ float g_V1[(size_t)MROWS * HIDP];   // V1 [6400][896]

// ---------------- PTX helpers ----------------
typedef unsigned long long ull;
__device__ __forceinline__ uint32_t smem_u32(const void* p) {
    uint32_t a;
    asm("{ .reg .u64 t; cvta.to.shared.u64 t, %1; cvt.u32.u64 %0, t; }" : "=r"(a) : "l"(p));
    return a;
}
__device__ __forceinline__ void cp_async16(uint32_t dst, const void* src) {
    asm volatile("cp.async.cg.shared.global [%0], [%1], 16;" :: "r"(dst), "l"(src));
}
#define CP_COMMIT() asm volatile("cp.async.commit_group;" ::: "memory")
__device__ __forceinline__ void ffma2(ull& d, ull a, ull b) {
    asm("fma.rn.f32x2 %0, %1, %2, %0;" : "+l"(d) : "l"(a), "l"(b));
}
__device__ __forceinline__ ull pack2(float x) {
    ull r; asm("mov.b64 %0, {%1, %1};" : "=l"(r) : "f"(x)); return r;
}

// ---------------- kernel 2: clips -> Xc [2320][6400] (k-major) ----------------
__global__ void transposeA_kernel(const float* __restrict__ inp) {
    __shared__ float tile[32][51];
    int i  = blockIdx.x;
    int d0 = blockIdx.y * 32;
    int tid = threadIdx.x;  // 256
    for (int p = tid; p < 32 * CLIP; p += 256) {
        int dd = p / CLIP, s = p % CLIP;
        int d = d0 + dd;
        tile[dd][s] = (d < DIN) ? inp[((long)i * DIN + d) * CLIP + s] : 0.f;
    }
    __syncthreads();
    for (int p = tid; p < 32 * CLIP; p += 256) {
        int dd = p / CLIP, s = p % CLIP;
        int d = d0 + dd;
        if (d < DINP)
            g_Xc[(long)d * MROWS + i * CLIP + s] = tile[dd][s];
    }
}

// ---------------- kernel 3: W1 -> Bt [2320][896] coalesced transpose ----------
__global__ void transposeB_kernel(const float* __restrict__ W1) {
    __shared__ float tile[32][33];
    int k0 = blockIdx.x * 32;
    int n0 = blockIdx.y * 32;
    int tx = threadIdx.x & 31;
    int ty = threadIdx.x >> 5;     // 0..7
#pragma unroll
    for (int r = 0; r < 4; r++) {
        int n = n0 + ty + r * 8;
        int k = k0 + tx;
        tile[ty + r * 8][tx] = (n < HID && k < DIN) ? W1[(long)n * DIN + k] : 0.f;
    }
    __syncthreads();
#pragma unroll
    for (int r = 0; r < 4; r++) {
        int k = k0 + ty + r * 8;
        int n = n0 + tx;
        if (k < DINP && n < HIDP)
            g_Bt[(long)k * HIDP + n] = tile[tx][ty + r * 8];
    }
}

// ---------------- kernel 4: fp32x2 FFMA GEMM (round-12 core, bit-exact) -------
// BM=32, BN=128, BK=16, 128 threads, 3-stage cp.async, grid 1400, occ 4.
#define BK 16
#define NST 3
#define A_STG 2048                 // 16 kk * 128B (32 m floats)
#define B_STG 8192                 // 16 kk * 512B (128 n)
#define STG (A_STG + B_STG)        // 10240
#define GEMM_SMEM (NST * STG)      // 30720

__global__ __launch_bounds__(128, 4) void gemm_kernel() {
    extern __shared__ char dsm[];
    uint32_t sb = smem_u32(dsm);
    int tid = threadIdx.x;
    int m0 = blockIdx.x * 32;
    int n0 = blockIdx.y * 128;
    int tx = tid & 15;         // 16 over N (8 cols each)
    int ty = tid >> 4;         // 8 over M (4 rows each)

    ull acc[4][4];
#pragma unroll
    for (int r = 0; r < 4; r++)
#pragma unroll
        for (int q = 0; q < 4; q++) acc[r][q] = 0ull;

    const float* Ab = g_Xc + m0;
    const float* Bb = g_Bt + n0;
    int akk = tid >> 3, acc4 = (tid & 7) * 4;   // A loader: 128 items of 16B

    // prologue: chunks 0..NST-2
#pragma unroll
    for (int c = 0; c < NST - 1; ++c) {
        uint32_t st = sb + c * STG;
        long k0 = (long)c * BK;
        cp_async16(st + akk * 128 + acc4 * 4,
                   Ab + (k0 + akk) * MROWS + acc4);
#pragma unroll
        for (int j = 0; j < 4; ++j) {
            int id = tid + 128 * j;
            int kk = id >> 5, cc = id & 31;
            cp_async16(st + A_STG + kk * 512 + cc * 16,
                       Bb + (k0 + kk) * HIDP + cc * 4);
        }
        CP_COMMIT();
    }

    for (int c = 0; c < NCH; ++c) {
        int cl = c + NST - 1;
        if (cl < NCH) {
            uint32_t st = sb + (cl % NST) * STG;
            long k0 = (long)cl * BK;
            cp_async16(st + akk * 128 + acc4 * 4,
                       Ab + (k0 + akk) * MROWS + acc4);
#pragma unroll
            for (int j = 0; j < 4; ++j) {
                int id = tid + 128 * j;
                int kk = id >> 5, cc = id & 31;
                cp_async16(st + A_STG + kk * 512 + cc * 16,
                           Bb + (k0 + kk) * HIDP + cc * 4);
            }
        }
        CP_COMMIT();
        asm volatile("cp.async.wait_group %0;" :: "n"(NST - 1) : "memory");
        __syncthreads();

        const char* aT = dsm + (c % NST) * STG;
        const char* bT = aT + A_STG;
#pragma unroll
        for (int kk = 0; kk < BK; ++kk) {
            float4 a = *(const float4*)(aT + kk * 128 + ty * 16);
            ulonglong2 bv0 = *(const ulonglong2*)(bT + kk * 512 + tx * 16);
            ulonglong2 bv1 = *(const ulonglong2*)(bT + kk * 512 + 256 + tx * 16);
            ull ar[4];
            ar[0] = pack2(a.x); ar[1] = pack2(a.y);
            ar[2] = pack2(a.z); ar[3] = pack2(a.w);
            ull bq[4] = {bv0.x, bv0.y, bv1.x, bv1.y};
#pragma unroll
            for (int r = 0; r < 4; r++)
#pragma unroll
                for (int q = 0; q < 4; q++)
                    ffma2(acc[r][q], ar[r], bq[q]);
        }
        __syncthreads();
    }

    // epilogue
#pragma unroll
    for (int r = 0; r < 4; r++) {
        long m = m0 + ty * 4 + r;
        float2 f0 = *(float2*)&acc[r][0];
        float2 f1 = *(float2*)&acc[r][1];
        float2 f2 = *(float2*)&acc[r][2];
        float2 f3 = *(float2*)&acc[r][3];
        *(float4*)&g_V1[m * HIDP + n0 + tx * 4]      = make_float4(f0.x, f0.y, f1.x, f1.y);
        *(float4*)&g_V1[m * HIDP + n0 + 64 + tx * 4] = make_float4(f2.x, f2.y, f3.x, f3.y);
    }
}

// ---------------- kernel 5: heterogeneous grid — scan CTAs + paste CTAs -------
// bid < 128: scan v3 (unchanged arithmetic). bid >= 128: pure paste copy,
// running concurrently on spare SM slots (2 CTAs/SM via launch_bounds(256,2)).
__global__ __launch_bounds__(256, 2) void scanpaste_kernel(
    const float* __restrict__ inp,
    const int*   __restrict__ idx,
    const float* __restrict__ b1,
    const float* __restrict__ W2,
    const float* __restrict__ b2,
    const float* __restrict__ Wc,
    const float* __restrict__ bc,
    float*       __restrict__ out)
{
    int tid = threadIdx.x;

    if (blockIdx.x >= BATCH) {
        // ---------------- paste CTA ----------------
        float* outX = out + BATCH * NC;
        unsigned int base = (blockIdx.x - BATCH) * 256u + (unsigned)tid;
        for (unsigned int P = base; P < NTOT4; P += NPCTA * 256u) {
            unsigned int i   = P / IPB;
            unsigned int rem = P - i * IPB;
            unsigned int d   = rem / 75u;
            unsigned int c4  = rem - d * 75u;
            int id = idx[i];
            const float* src = inp + ((long)i * DIN + d) * CLIP;
            float4 v;
            float* vv = (float*)&v;
#pragma unroll
            for (int u = 0; u < 4; u++) {
                int ss = (int)c4 * 4 + u - id;
                vv[u] = (ss >= 0 && ss < CLIP) ? src[ss] : 0.f;
            }
            *(float4*)&outX[((long)i * DIN + d) * TSTEPS + c4 * 4] = v;
        }
        return;
    }

    // ---------------- scan CTA (arithmetic identical to round 12) ----------
    __shared__ float wpart[2][8][11];
    int i = blockIdx.x;

    int  jj[4]; bool jv[4];
#pragma unroll
    for (int r = 0; r < 4; r++) { jj[r] = tid + 256 * r; jv[r] = (jj[r] < HID); }

    float w2r[4][NC], wcr[4], b1r[4];
#pragma unroll
    for (int r = 0; r < 4; r++) {
        if (jv[r]) {
#pragma unroll
            for (int k = 0; k < NC; k++) w2r[r][k] = W2[k * HID + jj[r]];
            wcr[r] = Wc[jj[r]];
            b1r[r] = b1[jj[r]];
        } else {
#pragma unroll
            for (int k = 0; k < NC; k++) w2r[r][k] = 0.f;
            wcr[r] = 0.f; b1r[r] = 0.f;
        }
    }

    float h1m[4] = {0.f, 0.f, 0.f, 0.f};
    float h1s[4] = {0.f, 0.f, 0.f, 0.f};

    float cm = 0.f, cs = 0.f, bgt = 1.f;
    float wc0 = Wc[800], wc1 = Wc[801], wc2 = Wc[802], wc3 = Wc[803];
    float bc0 = bc[0];

    float h2m = 0.f, h2s = 0.f, sum2 = 0.f, my_b2 = 0.f;
    if (tid < 10) my_b2 = b2[tid];

    int myidx = idx[i];
    const float* v1base = &g_V1[(long)i * CLIP * HIDP];

    float vp[4] = {0.f, 0.f, 0.f, 0.f};
    {
        int s0 = 0 - myidx;
        if (s0 >= 0 && s0 < CLIP) {
            const float* v1 = v1base + (long)s0 * HIDP;
#pragma unroll
            for (int r = 0; r < 4; r++) if (jv[r]) vp[r] = v1[jj[r]];
        }
    }

    for (int t = 0; t < TSTEPS; t++) {
        float g = (t == 0) ? 1.f : cs;
        int s = t - myidx;
        bool act = (s >= 0) && (s < CLIP) && (g != 0.f);

        float part[11];
#pragma unroll
        for (int k = 0; k < 11; k++) part[k] = 0.f;

#pragma unroll
        for (int r = 0; r < 4; r++) {
            if (jv[r]) {
                float v = act ? vp[r] : 0.f;   // gate is exactly 1 when act
                float m = h1m[r] * 0.1f * (1.f - h1s[r]) + v + b1r[r];
                h1m[r] = m;
                float sp = (m > 0.5f) ? 1.f : 0.f;
                h1s[r] = sp;
                if (sp != 0.f) {
#pragma unroll
                    for (int k = 0; k < 10; k++) part[k] += w2r[r][k];
                    part[10] += wcr[r];
                }
            }
        }

        float vn[4] = {0.f, 0.f, 0.f, 0.f};
        int sn = t + 1 - myidx;
        if (t + 1 < TSTEPS && sn >= 0 && sn < CLIP) {
            const float* v1n = v1base + (long)sn * HIDP;
#pragma unroll
            for (int r = 0; r < 4; r++) if (jv[r]) vn[r] = __ldg(&v1n[jj[r]]);
        }

#pragma unroll
        for (int k = 0; k < 11; k++) {
#pragma unroll
            for (int off = 16; off; off >>= 1)
                part[k] += __shfl_down_sync(0xffffffffu, part[k], off);
        }
        int buf = t & 1;
        if ((tid & 31) == 0) {
#pragma unroll
            for (int k = 0; k < 11; k++) wpart[buf][tid >> 5][k] = part[k];
        }
        __syncthreads();   // the ONLY barrier per step

        {
            float red = 0.f;
#pragma unroll
            for (int w = 0; w < 8; w++) red += wpart[buf][w][10];
            float csprev = cs;
            if (csprev == 1.f) bgt += 1.f;
            float fq = wc0
                     + (((t % 2)   == 0) ? wc1 : 0.f)
                     + (((t % 10)  == 0) ? wc2 : 0.f)
                     + (((t % 100) == 0) ? wc3 : 0.f);
            cm = cm * 0.1f * (1.f - csprev) + red + fq + bc0;
            cs = (cm > 0.5f) ? 1.f : 0.f;
        }

        if (tid < 10) {
            float red = 0.f;
#pragma unroll
            for (int w = 0; w < 8; w++) red += wpart[buf][w][tid];
            float m = h2m * 0.1f * (1.f - h2s) + red + my_b2;
            h2m = m;
            h2s = (m > 0.5f) ? 1.f : 0.f;
            sum2 += h2s;
        }

#pragma unroll
        for (int r = 0; r < 4; r++) vp[r] = vn[r];
    }

    if (tid < 10) out[i * NC + tid] = sum2 / bgt;
}

// ---------------- launcher ----------------
extern "C" void kernel_launch(void* const* d_in, const int* in_sizes, int n_in,
                              void* d_out, int out_size) {
    const float* inp = (const float*)d_in[0];
    const int*   idx = (const int*)d_in[2];
    const float* W1  = (const float*)d_in[3];
    const float* b1  = (const float*)d_in[4];
    const float* W2  = (const float*)d_in[5];
    const float* b2  = (const float*)d_in[6];
    const float* Wc  = (const float*)d_in[7];
    const float* bc  = (const float*)d_in[8];
    float* out = (float*)d_out;

    cudaFuncSetAttribute(gemm_kernel, cudaFuncAttributeMaxDynamicSharedMemorySize,
                         GEMM_SMEM);

    {
        dim3 grid(BATCH, (DINP + 31) / 32);
        transposeA_kernel<<<grid, 256>>>(inp);
    }
    {
        dim3 grid((DINP + 31) / 32, (HIDP + 31) / 32);
        transposeB_kernel<<<grid, 256>>>(W1);
    }
    {
        dim3 grid(MROWS / 32, HIDP / 128);
        gemm_kernel<<<grid, 128, GEMM_SMEM>>>();
    }
    scanpaste_kernel<<<BATCH + NPCTA, 256>>>(inp, idx, b1, W2, b2, Wc, bc, out);
}